// round 13
// baseline (speedup 1.0000x reference)
#include <cuda_runtime.h>
#include <cuda_bf16.h>

// SRLoss: loss = mean((inp - avgpool10x10(output))^2) + BCE(output, target)
// output, target: [32,1,1280,1280] f32 ; inp: [32,1,128,128] f32 ; out: 1 f32
//
// Single fused kernel (420 MB HBM traffic, DRAM-bound):
//   grid = 32*128 blocks (one per (batch, pooled_row) band of 10 image rows)
//   block = 320 threads, each owns one float4 column of the 1280-wide band.
//   Per thread: 10 coalesced float4 loads of output + target, BCE inline,
//   float4 column sum for pooling. Column sums -> smem -> 128 pooled bins
//   -> MSE vs inp. Block partials -> double atomics; the LAST block (via a
//   completion counter) computes the final loss, writes d_out, and resets
//   the accumulators so the kernel stays deterministic under graph replay.
//   (Replaces the separate init/finalize launches, which cost ~7.5 us.)

#define BATCH 32
#define IMH   1280
#define IMW   1280
#define PH    128
#define PW    128
#define NBLK  (BATCH * PH)
#define NBCE  ((double)BATCH * IMH * IMW)
#define NMSE  ((double)BATCH * PH * PW)

__device__ double       g_bce_sum;   // zero-init at module load; last block re-zeros
__device__ double       g_mse_sum;
__device__ unsigned int g_count;

__device__ __forceinline__ float bce_term(float o, float t) {
    // target*log(om) + (1-target)*log(oc), exact-zero -> log(1e-20)
    const float LOG_EPS = -46.0517019f;
    float lo = (o == 0.0f) ? LOG_EPS : __logf(o);
    float oc = 1.0f - o;
    float lc = (oc == 0.0f) ? LOG_EPS : __logf(oc);
    // t*lo + (1-t)*lc == lc + t*(lo - lc)
    return fmaf(t, lo - lc, lc);
}

__global__ __launch_bounds__(320) void srloss_fused_kernel(
    const float* __restrict__ out,
    const float* __restrict__ tgt,
    const float* __restrict__ inp,
    float* __restrict__ result)
{
    const int bid = blockIdx.x;
    const int b   = bid >> 7;      // / 128 pooled rows
    const int pr  = bid & 127;
    const int tid = threadIdx.x;   // 0..319, one float4 column each

    __shared__ float colsum[IMW];      // per-column sums over the 10 rows
    __shared__ float warp_bce[10];
    __shared__ float warp_mse[4];

    const size_t band_base = (size_t)b * (IMH * IMW) + (size_t)pr * 10 * IMW;
    const float4* o4 = reinterpret_cast<const float4*>(out + band_base) + tid;
    const float4* t4 = reinterpret_cast<const float4*>(tgt + band_base) + tid;

    // hoist the inp element load (only threads 0..127 use it after the barrier)
    float inp_v = 0.f;
    if (tid < 128)
        inp_v = inp[(size_t)b * (PH * PW) + pr * PW + tid];

    float4 cs = make_float4(0.f, 0.f, 0.f, 0.f);
    float bce = 0.f;

    #pragma unroll
    for (int r = 0; r < 10; r++) {
        float4 o = o4[r * (IMW / 4)];
        float4 t = t4[r * (IMW / 4)];
        cs.x += o.x; cs.y += o.y; cs.z += o.z; cs.w += o.w;
        bce += bce_term(o.x, t.x);
        bce += bce_term(o.y, t.y);
        bce += bce_term(o.z, t.z);
        bce += bce_term(o.w, t.w);
    }

    reinterpret_cast<float4*>(colsum)[tid] = cs;

    // warp-reduce BCE partial (10 warps)
    #pragma unroll
    for (int off = 16; off > 0; off >>= 1)
        bce += __shfl_down_sync(0xffffffffu, bce, off);
    if ((tid & 31) == 0) warp_bce[tid >> 5] = bce;

    __syncthreads();

    // threads 0..127: one pooled bin each = sum of 10 column sums / 100
    float msep = 0.f;
    if (tid < 128) {
        float s = 0.f;
        #pragma unroll
        for (int j = 0; j < 10; j++) s += colsum[tid * 10 + j];
        float pooled = s * 0.01f;
        float d = inp_v - pooled;
        msep = d * d;
    }
    #pragma unroll
    for (int off = 16; off > 0; off >>= 1)
        msep += __shfl_down_sync(0xffffffffu, msep, off);
    if (tid < 128 && (tid & 31) == 0) warp_mse[tid >> 5] = msep;

    __syncthreads();

    if (tid == 0) {
        float bsum = 0.f;
        #pragma unroll
        for (int i = 0; i < 10; i++) bsum += warp_bce[i];
        float msum = warp_mse[0] + warp_mse[1] + warp_mse[2] + warp_mse[3];
        atomicAdd(&g_bce_sum, (double)bsum);
        atomicAdd(&g_mse_sum, (double)msum);
        __threadfence();
        unsigned int c = atomicAdd(&g_count, 1u);
        if (c == (unsigned int)(NBLK - 1)) {
            // all other blocks' atomics are globally visible (fence before
            // their counter bump); we observed the final counter value.
            __threadfence();
            double mse = g_mse_sum / NMSE;
            double bce_m = -g_bce_sum / NBCE;
            result[0] = (float)(mse + bce_m);
            // reset for the next (graph-replayed) call
            g_bce_sum = 0.0;
            g_mse_sum = 0.0;
            g_count   = 0u;
        }
    }
}

extern "C" void kernel_launch(void* const* d_in, const int* in_sizes, int n_in,
                              void* d_out, int out_size) {
    const float* output = (const float*)d_in[0];
    const float* target = (const float*)d_in[1];
    const float* inp    = (const float*)d_in[2];
    float* out = (float*)d_out;

    srloss_fused_kernel<<<NBLK, 320>>>(output, target, inp, out);
}

// round 14
// speedup vs baseline: 1.0371x; 1.0371x over previous
#include <cuda_runtime.h>
#include <cuda_bf16.h>

// SRLoss: loss = mean((inp - avgpool10x10(output))^2) + BCE(output, target)
// output, target: [32,1,1280,1280] f32 ; inp: [32,1,128,128] f32 ; out: 1 f32
//
// Persistent fused kernel (420 MB HBM traffic, DRAM-bound):
//   grid = 152*6 = 912 blocks of 320 threads (6 blocks/SM via launch_bounds).
//   Each block loops over "bands" (one band = batch b, pooled row pr = 10
//   contiguous image rows = 12800 contiguous floats) with stride gridDim.x.
//   Per band: each thread streams one float4 column over 10 rows (__ldcs),
//   BCE inline, column sums -> double-buffered smem (one barrier per band)
//   -> 128 pooled bins -> MSE vs inp, accumulated in registers across bands.
//   One shuffle-reduction + two double atomics per BLOCK (not per band).
//   Last block (completion counter) finalizes into d_out and resets globals
//   so the kernel is deterministic under graph replay.

#define BATCH 32
#define IMH   1280
#define IMW   1280
#define PH    128
#define PW    128
#define NBAND (BATCH * PH)             // 4096 bands, each 12800 floats
#define NBLK  912                      // 152 SMs * 6 blocks
#define NBCE  ((double)BATCH * IMH * IMW)
#define NMSE  ((double)BATCH * PH * PW)

__device__ double       g_bce_sum;     // zero at module load; last block re-zeros
__device__ double       g_mse_sum;
__device__ unsigned int g_count;

__device__ __forceinline__ float bce_term(float o, float t) {
    // target*log(om) + (1-target)*log(oc), exact-zero -> log(1e-20)
    const float LOG_EPS = -46.0517019f;
    float lo = (o == 0.0f) ? LOG_EPS : __logf(o);
    float oc = 1.0f - o;
    float lc = (oc == 0.0f) ? LOG_EPS : __logf(oc);
    return fmaf(t, lo - lc, lc);       // lc + t*(lo - lc)
}

__global__ __launch_bounds__(320, 6) void srloss_fused_kernel(
    const float* __restrict__ out,
    const float* __restrict__ tgt,
    const float* __restrict__ inp,
    float* __restrict__ result)
{
    const int tid = threadIdx.x;       // 0..319, one float4 column each

    __shared__ float colsum[2][IMW];   // double-buffered per-column sums
    __shared__ float warp_bce[10];
    __shared__ float warp_mse[4];

    float bce_acc = 0.f;               // across all bands this block handles
    float mse_acc = 0.f;               // meaningful for tid < 128 only

    int parity = 0;
    for (int band = blockIdx.x; band < NBAND; band += NBLK) {
        const size_t base = (size_t)band * (10 * IMW);
        const float4* o4 = reinterpret_cast<const float4*>(out + base) + tid;
        const float4* t4 = reinterpret_cast<const float4*>(tgt + base) + tid;

        // hoist inp element (used by tid<128 after the barrier)
        float inp_v = 0.f;
        if (tid < 128)
            inp_v = __ldg(&inp[band * PW + tid]);

        float4 cs = make_float4(0.f, 0.f, 0.f, 0.f);
        #pragma unroll
        for (int r = 0; r < 10; r++) {
            float4 o = __ldcs(&o4[r * (IMW / 4)]);
            float4 t = __ldcs(&t4[r * (IMW / 4)]);
            cs.x += o.x; cs.y += o.y; cs.z += o.z; cs.w += o.w;
            bce_acc += bce_term(o.x, t.x);
            bce_acc += bce_term(o.y, t.y);
            bce_acc += bce_term(o.z, t.z);
            bce_acc += bce_term(o.w, t.w);
        }

        reinterpret_cast<float4*>(colsum[parity])[tid] = cs;
        __syncthreads();
        // (next iteration writes the other buffer; the barrier of iteration
        //  i+1 orders this iteration's reads before iteration i+2's writes)

        if (tid < 128) {
            float s = 0.f;
            #pragma unroll
            for (int j = 0; j < 10; j++) s += colsum[parity][tid * 10 + j];
            float d = inp_v - s * 0.01f;
            mse_acc += d * d;
        }
        parity ^= 1;
    }

    // -------- per-block reduction (once, not per band) --------
    #pragma unroll
    for (int off = 16; off > 0; off >>= 1)
        bce_acc += __shfl_down_sync(0xffffffffu, bce_acc, off);
    if ((tid & 31) == 0) warp_bce[tid >> 5] = bce_acc;

    #pragma unroll
    for (int off = 16; off > 0; off >>= 1)
        mse_acc += __shfl_down_sync(0xffffffffu, mse_acc, off);
    if (tid < 128 && (tid & 31) == 0) warp_mse[tid >> 5] = mse_acc;

    __syncthreads();

    if (tid == 0) {
        float bsum = 0.f;
        #pragma unroll
        for (int i = 0; i < 10; i++) bsum += warp_bce[i];
        float msum = warp_mse[0] + warp_mse[1] + warp_mse[2] + warp_mse[3];
        atomicAdd(&g_bce_sum, (double)bsum);
        atomicAdd(&g_mse_sum, (double)msum);
        __threadfence();
        unsigned int c = atomicAdd(&g_count, 1u);
        if (c == (unsigned int)(NBLK - 1)) {
            __threadfence();
            double mse = g_mse_sum / NMSE;
            double bce = -g_bce_sum / NBCE;
            result[0] = (float)(mse + bce);
            // reset for the next graph replay
            g_bce_sum = 0.0;
            g_mse_sum = 0.0;
            g_count   = 0u;
        }
    }
}

extern "C" void kernel_launch(void* const* d_in, const int* in_sizes, int n_in,
                              void* d_out, int out_size) {
    const float* output = (const float*)d_in[0];
    const float* target = (const float*)d_in[1];
    const float* inp    = (const float*)d_in[2];
    float* out = (float*)d_out;

    srloss_fused_kernel<<<NBLK, 320>>>(output, target, inp, out);
}

// round 15
// speedup vs baseline: 1.0412x; 1.0040x over previous
#include <cuda_runtime.h>
#include <cuda_bf16.h>

// SRLoss: loss = mean((inp - avgpool10x10(output))^2) + BCE(output, target)
// output, target: [32,1,1280,1280] f32 ; inp: [32,1,128,128] f32 ; out: 1 f32
//
// Persistent fused kernel (420 MB HBM traffic, DRAM-bound):
//   grid = 152*6 = 912 blocks of 320 threads (6 blocks/SM via launch_bounds).
//   Each block loops over "bands" (one band = batch b, pooled row pr = 10
//   contiguous image rows = 12800 contiguous floats) with stride gridDim.x.
//   Per band: each thread streams one float4 column over 10 rows (__ldcs),
//   BCE inline, column sums -> double-buffered smem (one barrier per band)
//   -> 128 pooled bins -> MSE vs inp, accumulated in registers across bands.
//   One shuffle-reduction + two double atomics per BLOCK (not per band).
//   Last block (completion counter) finalizes into d_out and resets globals
//   so the kernel is deterministic under graph replay.

#define BATCH 32
#define IMH   1280
#define IMW   1280
#define PH    128
#define PW    128
#define NBAND (BATCH * PH)             // 4096 bands, each 12800 floats
#define NBLK  912                      // 152 SMs * 6 blocks
#define NBCE  ((double)BATCH * IMH * IMW)
#define NMSE  ((double)BATCH * PH * PW)

__device__ double       g_bce_sum;     // zero at module load; last block re-zeros
__device__ double       g_mse_sum;
__device__ unsigned int g_count;

__device__ __forceinline__ float bce_term(float o, float t) {
    // target*log(om) + (1-target)*log(oc), exact-zero -> log(1e-20)
    const float LOG_EPS = -46.0517019f;
    float lo = (o == 0.0f) ? LOG_EPS : __logf(o);
    float oc = 1.0f - o;
    float lc = (oc == 0.0f) ? LOG_EPS : __logf(oc);
    return fmaf(t, lo - lc, lc);       // lc + t*(lo - lc)
}

__global__ __launch_bounds__(320, 6) void srloss_fused_kernel(
    const float* __restrict__ out,
    const float* __restrict__ tgt,
    const float* __restrict__ inp,
    float* __restrict__ result)
{
    const int tid = threadIdx.x;       // 0..319, one float4 column each

    __shared__ float colsum[2][IMW];   // double-buffered per-column sums
    __shared__ float warp_bce[10];
    __shared__ float warp_mse[4];

    float bce_acc = 0.f;               // across all bands this block handles
    float mse_acc = 0.f;               // meaningful for tid < 128 only

    int parity = 0;
    for (int band = blockIdx.x; band < NBAND; band += NBLK) {
        const size_t base = (size_t)band * (10 * IMW);
        const float4* o4 = reinterpret_cast<const float4*>(out + base) + tid;
        const float4* t4 = reinterpret_cast<const float4*>(tgt + base) + tid;

        // hoist inp element (used by tid<128 after the barrier)
        float inp_v = 0.f;
        if (tid < 128)
            inp_v = __ldg(&inp[band * PW + tid]);

        float4 cs = make_float4(0.f, 0.f, 0.f, 0.f);
        #pragma unroll
        for (int r = 0; r < 10; r++) {
            float4 o = __ldcs(&o4[r * (IMW / 4)]);
            float4 t = __ldcs(&t4[r * (IMW / 4)]);
            cs.x += o.x; cs.y += o.y; cs.z += o.z; cs.w += o.w;
            bce_acc += bce_term(o.x, t.x);
            bce_acc += bce_term(o.y, t.y);
            bce_acc += bce_term(o.z, t.z);
            bce_acc += bce_term(o.w, t.w);
        }

        reinterpret_cast<float4*>(colsum[parity])[tid] = cs;
        __syncthreads();
        // (next iteration writes the other buffer; the barrier of iteration
        //  i+1 orders this iteration's reads before iteration i+2's writes)

        if (tid < 128) {
            float s = 0.f;
            #pragma unroll
            for (int j = 0; j < 10; j++) s += colsum[parity][tid * 10 + j];
            float d = inp_v - s * 0.01f;
            mse_acc += d * d;
        }
        parity ^= 1;
    }

    // -------- per-block reduction (once, not per band) --------
    #pragma unroll
    for (int off = 16; off > 0; off >>= 1)
        bce_acc += __shfl_down_sync(0xffffffffu, bce_acc, off);
    if ((tid & 31) == 0) warp_bce[tid >> 5] = bce_acc;

    #pragma unroll
    for (int off = 16; off > 0; off >>= 1)
        mse_acc += __shfl_down_sync(0xffffffffu, mse_acc, off);
    if (tid < 128 && (tid & 31) == 0) warp_mse[tid >> 5] = mse_acc;

    __syncthreads();

    if (tid == 0) {
        float bsum = 0.f;
        #pragma unroll
        for (int i = 0; i < 10; i++) bsum += warp_bce[i];
        float msum = warp_mse[0] + warp_mse[1] + warp_mse[2] + warp_mse[3];
        atomicAdd(&g_bce_sum, (double)bsum);
        atomicAdd(&g_mse_sum, (double)msum);
        __threadfence();
        unsigned int c = atomicAdd(&g_count, 1u);
        if (c == (unsigned int)(NBLK - 1)) {
            __threadfence();
            double mse = g_mse_sum / NMSE;
            double bce = -g_bce_sum / NBCE;
            result[0] = (float)(mse + bce);
            // reset for the next graph replay
            g_bce_sum = 0.0;
            g_mse_sum = 0.0;
            g_count   = 0u;
        }
    }
}

extern "C" void kernel_launch(void* const* d_in, const int* in_sizes, int n_in,
                              void* d_out, int out_size) {
    const float* output = (const float*)d_in[0];
    const float* target = (const float*)d_in[1];
    const float* inp    = (const float*)d_in[2];
    float* out = (float*)d_out;

    srloss_fused_kernel<<<NBLK, 320>>>(output, target, inp, out);
}